// round 15
// baseline (speedup 1.0000x reference)
#include <cuda_runtime.h>

#define NB  4
#define NSQ 512
#define NSK 512
#define ND  512
#define NS  128

typedef unsigned long long ull;

// ---- packed f32x2 helpers ----
__device__ __forceinline__ void fma2(ull& d, ull a, ull b) {
    asm("fma.rn.f32x2 %0, %1, %2, %0;" : "+l"(d) : "l"(a), "l"(b));
}
__device__ __forceinline__ ull add2(ull a, ull b) {
    ull r; asm("add.rn.f32x2 %0, %1, %2;" : "=l"(r) : "l"(a), "l"(b)); return r;
}
__device__ __forceinline__ ull pack2(float x, float y) {
    ull r; asm("mov.b64 %0, {%1, %2};" : "=l"(r) : "f"(x), "f"(y)); return r;
}
__device__ __forceinline__ float2 unpack2(ull v) {
    float2 r; asm("mov.b64 {%0, %1}, %2;" : "=f"(r.x), "=f"(r.y) : "l"(v)); return r;
}

#define SMASK 0x7fffffff7fffffffULL

// ---- scratch (allocation-free) ----
__device__ __align__(16) float g_Wqh[ND * NS];
__device__ __align__(16) float g_Wkh[ND * NS];
__device__ __align__(16) float g_cA[NS];
__device__ __align__(16) float g_cK[NS];
__device__ __align__(16) float g_sg[NS];            // +-0.5 by sign of w2
__device__ __align__(16) float g_A2[NB * NSQ * NS]; // (q@Wqh + cA) * w2
__device__ __align__(16) float g_K2[NB * NSK * NS]; // (k@Wkh + cK) * w2
__device__ __align__(16) float g_CA[NB * NSQ];      // 0.5 * rowsum(A2)
__device__ __align__(16) float g_CK[NB * NSK];      // 0.5 * rowsum(K2)

// ---------------------------------------------------------------------------
// fold: Wqh = Wq @ W1[:S], Wkh = Wk @ W1[S:]  (+ bias/sg in block x==64)
// ---------------------------------------------------------------------------
__global__ void fold_kernel(const float* __restrict__ Wq,
                            const float* __restrict__ Wk,
                            const float* __restrict__ W1,
                            const float* __restrict__ bq,
                            const float* __restrict__ bk,
                            const float* __restrict__ b1,
                            const float* __restrict__ W2) {
    int v = blockIdx.y, s = threadIdx.x;
    if (blockIdx.x == 64) {
        if (v == 0) {
            float a = b1[s];
#pragma unroll 8
            for (int t = 0; t < NS; t++) a = fmaf(bq[t], W1[t * NS + s], a);
            g_cA[s] = a;
            g_sg[s] = (W2[s] >= 0.f) ? 0.5f : -0.5f;
        } else {
            float c = 0.f;
#pragma unroll 8
            for (int t = 0; t < NS; t++) c = fmaf(bk[t], W1[(NS + t) * NS + s], c);
            g_cK[s] = c;
        }
        return;
    }
    int d0 = blockIdx.x * 8;
    __shared__ float wr[8][NS];
    const float* Wsrc = v ? Wk : Wq;
#pragma unroll
    for (int j = 0; j < 8; j++) wr[j][s] = Wsrc[(d0 + j) * NS + s];
    __syncthreads();
    const float* W1p = W1 + (v ? NS * NS : 0);
    float acc[8] = {};
#pragma unroll 8
    for (int t = 0; t < NS; t++) {
        float w = W1p[t * NS + s];
#pragma unroll
        for (int j = 0; j < 8; j++) acc[j] = fmaf(wr[j][t], w, acc[j]);
    }
    float* O = v ? g_Wkh : g_Wqh;
#pragma unroll
    for (int j = 0; j < 8; j++) O[(d0 + j) * NS + s] = acc[j];
}

// ---------------------------------------------------------------------------
// proj: A2 = (X @ Wfold + cb) * w2, plus CA = 0.5*rowsum(A2)  (unchanged)
// ---------------------------------------------------------------------------
#define ASP 36
#define BSP 132

__global__ __launch_bounds__(256) void proj_kernel(const float* __restrict__ Xq,
                                                   const float* __restrict__ Xk,
                                                   const float* __restrict__ W2) {
    int v = blockIdx.y;
    const float* X    = v ? Xk : Xq;
    const float* Wf   = v ? g_Wkh : g_Wqh;
    const float* bias = v ? g_cK : g_cA;
    float* O          = v ? g_K2 : g_A2;
    float* CS         = v ? g_CK : g_CA;

    int m0  = blockIdx.x * 32;
    int tid = threadIdx.x;
    int w   = tid >> 5, lane = tid & 31;
    int qc  = lane >> 2, dc = lane & 3;

    __shared__ float As[16][ASP];
    __shared__ float Bs[16][BSP];
    __shared__ float red[8][32];

    int r  = tid >> 3, c2 = (tid & 7) * 2;
    int rb = tid >> 4, cw = (tid & 15) * 8;

    float2 xv = *(const float2*)&X[(m0 + r) * ND + c2];
    float4 w0 = *(const float4*)&Wf[rb * NS + cw];
    float4 w1 = *(const float4*)&Wf[rb * NS + cw + 4];

    ull acc[4][2] = {};
    int db = w * 16 + dc * 4;

    for (int t = 0; t < ND / 16; t++) {
        As[c2][r] = xv.x; As[c2 + 1][r] = xv.y;
        *(float4*)&Bs[rb][cw]     = w0;
        *(float4*)&Bs[rb][cw + 4] = w1;
        __syncthreads();
        if (t + 1 < ND / 16) {
            int k0 = (t + 1) * 16;
            xv = *(const float2*)&X[(m0 + r) * ND + k0 + c2];
            w0 = *(const float4*)&Wf[(k0 + rb) * NS + cw];
            w1 = *(const float4*)&Wf[(k0 + rb) * NS + cw + 4];
        }
#pragma unroll
        for (int kk = 0; kk < 16; kk++) {
            float4 a = *(float4*)&As[kk][qc * 4];
            ulonglong2 bv = *(ulonglong2*)&Bs[kk][db];
            ull p0 = pack2(a.x, a.x), p1 = pack2(a.y, a.y);
            ull p2 = pack2(a.z, a.z), p3 = pack2(a.w, a.w);
            fma2(acc[0][0], p0, bv.x); fma2(acc[0][1], p0, bv.y);
            fma2(acc[1][0], p1, bv.x); fma2(acc[1][1], p1, bv.y);
            fma2(acc[2][0], p2, bv.x); fma2(acc[2][1], p2, bv.y);
            fma2(acc[3][0], p3, bv.x); fma2(acc[3][1], p3, bv.y);
        }
        __syncthreads();
    }

    float4 cbv = *(const float4*)&bias[db];
    float4 w2v = *(const float4*)&W2[db];
    float rsum[4];
#pragma unroll
    for (int j = 0; j < 4; j++) {
        int row = m0 + qc * 4 + j;
        float2 p0 = unpack2(acc[j][0]), p1 = unpack2(acc[j][1]);
        float4 o;
        o.x = (p0.x + cbv.x) * w2v.x; o.y = (p0.y + cbv.y) * w2v.y;
        o.z = (p1.x + cbv.z) * w2v.z; o.w = (p1.y + cbv.w) * w2v.w;
        *(float4*)&O[row * NS + db] = o;
        rsum[j] = o.x + o.y + o.z + o.w;
    }
#pragma unroll
    for (int j = 0; j < 4; j++) {
        rsum[j] += __shfl_xor_sync(0xffffffffu, rsum[j], 1);
        rsum[j] += __shfl_xor_sync(0xffffffffu, rsum[j], 2);
    }
    if (dc == 0) {
#pragma unroll
        for (int j = 0; j < 4; j++) red[w][qc * 4 + j] = rsum[j];
    }
    __syncthreads();
    if (tid < 32) {
        float s = 0.f;
#pragma unroll
        for (int ww = 0; ww < 8; ww++) s += red[ww][tid];
        CS[m0 + tid] = 0.5f * s;
    }
}

// ---------------------------------------------------------------------------
// scores + softmax + attn write (R9 version) — unchanged
// ---------------------------------------------------------------------------
#define TQ  8
#define KT  64
#define KMP 132
#define SCP 516

__global__ __launch_bounds__(128) void score_kernel(const int* __restrict__ mask,
                                                    const float* __restrict__ b2,
                                                    float* __restrict__ attn_out) {
    extern __shared__ float sm[];
    float* qcs = sm;                    // TQ*NS  = 1024 f
    float* sgs = qcs + TQ * NS;         // 128 f
    float* cks = sgs + NS;              // 512 f
    float* cas = cks + NSK;             // 16 f
    float* kms = cas + 16;              // KT*KMP = 8448 f
    float* scT = kms + KT * KMP;        // TQ*516 = 4128 f

    int bx = blockIdx.x;
    int b  = bx >> 6;
    int q0 = (bx & 63) * TQ;
    int tid = threadIdx.x;
    int kk = tid & 63;
    int qh = (tid >> 6) * 4;            // 0 or 4

    {
        const float4* A4 = (const float4*)&g_A2[(b * NSQ + q0) * NS];
        ((float4*)qcs)[tid]       = A4[tid];
        ((float4*)qcs)[tid + 128] = A4[tid + 128];
        if (tid < 32) ((float4*)sgs)[tid] = ((const float4*)g_sg)[tid];
        ((float4*)cks)[tid] = ((const float4*)(g_CK + b * NSK))[tid];
        if (tid < TQ) cas[tid] = g_CA[b * NSQ + q0 + tid] + b2[0];
    }

    const float* qp = qcs + qh * NS;

    for (int k0 = 0; k0 < NSK; k0 += KT) {
        __syncthreads();
        const float4* K4 = (const float4*)&g_K2[(b * NSK + k0) * NS];
#pragma unroll
        for (int i = 0; i < 16; i++) {
            int idx = i * 128 + tid;
            int kr = idx >> 5, s4 = idx & 31;
            *(float4*)&kms[kr * KMP + s4 * 4] = K4[idx];
        }
        __syncthreads();

        ull acc[4] = {};
#pragma unroll 8
        for (int s = 0; s < NS; s += 4) {
            ulonglong2 kv = *(ulonglong2*)&kms[kk * KMP + s];
            ulonglong2 sg = *(ulonglong2*)&sgs[s];
#pragma unroll
            for (int q = 0; q < 4; q++) {
                ulonglong2 qv = *(ulonglong2*)&qp[q * NS + s];
                ull x0 = add2(qv.x, kv.x) & SMASK;
                ull x1 = add2(qv.y, kv.y) & SMASK;
                fma2(acc[q], sg.x, x0);
                fma2(acc[q], sg.y, x1);
            }
        }

        int kg = k0 + kk;
        float ckv = cks[kg];
        const int* mrow = mask + (b * NSQ + q0 + qh) * NSK + kg;
#pragma unroll
        for (int q = 0; q < 4; q++) {
            float2 p = unpack2(acc[q]);
            float s = p.x + p.y + cas[qh + q] + ckv;
            if (mrow[q * NSK] == 0) s = -1e9f;
            scT[(qh + q) * SCP + kg] = s;
        }
    }
    __syncthreads();

    // softmax: warp w handles q = 2w, 2w+1; write normalized attn to gmem
    {
        int w = tid >> 5, lane = tid & 31;
#pragma unroll
        for (int qq = 0; qq < 2; qq++) {
            int q = w * 2 + qq;
            float4 v[4];
            float mx = -3.0e38f;
#pragma unroll
            for (int j = 0; j < 4; j++) {
                v[j] = *(float4*)&scT[q * SCP + j * 128 + lane * 4];
                mx = fmaxf(mx, fmaxf(fmaxf(v[j].x, v[j].y), fmaxf(v[j].z, v[j].w)));
            }
#pragma unroll
            for (int o = 16; o; o >>= 1) mx = fmaxf(mx, __shfl_xor_sync(0xffffffffu, mx, o));
            float sum = 0.f;
#pragma unroll
            for (int j = 0; j < 4; j++) {
                v[j].x = __expf(v[j].x - mx); v[j].y = __expf(v[j].y - mx);
                v[j].z = __expf(v[j].z - mx); v[j].w = __expf(v[j].w - mx);
                sum += v[j].x + v[j].y + v[j].z + v[j].w;
            }
#pragma unroll
            for (int o = 16; o; o >>= 1) sum += __shfl_xor_sync(0xffffffffu, sum, o);
            float inv = 1.0f / sum;
            float* arow = attn_out + (b * NSQ + q0 + q) * NSK;
#pragma unroll
            for (int j = 0; j < 4; j++) {
                float4 wv;
                wv.x = v[j].x * inv; wv.y = v[j].y * inv;
                wv.z = v[j].z * inv; wv.w = v[j].w * inv;
                *(float4*)&arow[j * 128 + lane * 4] = wv;
            }
        }
    }
}

// ---------------------------------------------------------------------------
// AV GEMM on tensor cores, PERMUTED smem layouts -> vector fragment loads.
// BM=32 q x BN=128 d x BK=32, 256 thr, grid (4,16,4)=256 -> 2 CTA/SM.
//
// A layout (pad 40): a[row][kb+j] at row*40 + kb + 2*(j&3) + (j>>2)
//   -> (fa0, fa2) = one LDS.64 at row*40 + kb + 2t   (banks 8g+2t: distinct)
// B layout (pad 136): V[d = S+8n+g] at k*136 + S + 4g + n
//   -> fb[n=0..3] = one LDS.128 at k*136 + ds + 4g   (banks cover all 32)
// Loads per warp-tile: 48 scalar -> 8 LDS.64 + 8 LDS.128 (1:1 with 16 HMMA).
// ---------------------------------------------------------------------------
#define AT_PAD 40
#define BS_PAD 136
#define AT_BUF (32 * AT_PAD)          // 1280 floats per buffer
#define BS_BUF (32 * BS_PAD)          // 4352 floats per buffer
#define SMEM_AV ((2 * AT_BUF + 2 * BS_BUF) * 4)   // 45056 B

__device__ __forceinline__ uint4 rna4(uint4 u) {
    u.x += 0x1000u; u.y += 0x1000u; u.z += 0x1000u; u.w += 0x1000u;
    return u;
}

__global__ __launch_bounds__(256) void av_kernel(const float* __restrict__ attn,
                                                 const float* __restrict__ Vv,
                                                 float* __restrict__ out) {
    extern __shared__ float avsm[];
    float* At = avsm;                  // [2][32][AT_PAD] permuted
    float* Bs = avsm + 2 * AT_BUF;     // [2][32][BS_PAD] permuted

    int b  = blockIdx.z;
    int q0 = blockIdx.y * 32;
    int d0 = blockIdx.x * 128;
    int tid = threadIdx.x;
    int w = tid >> 5, lane = tid & 31;
    int g = lane >> 2, t = lane & 3;
    int qs = (w >> 2) * 16;            // warp q-strip (0, 16)
    int ds = (w & 3) * 32;             // warp d-strip (0, 32, 64, 96)

    const float* Ab = attn + (b * NSQ + q0) * NSK;
    const float* Vb = Vv + b * NSK * ND + d0;

    int ar = tid >> 3, akc = (tid & 7) * 4;   // attn: q=ar, k chunk [akc, akc+4)
    int vr = tid >> 3, vc = (tid & 7) * 16;   // V: k=vr, d chunk [vc, vc+16)

    // permuted staging bases
    int abase = ar * AT_PAD + (akc & ~7) + ((akc & 4) ? 1 : 0);
    int bbase = vr * BS_PAD + (vc & ~31) + ((vc & 16) ? 2 : 0);

    // preload tile 0
    uint4 a0v = rna4(*(const uint4*)&Ab[ar * NSK + akc]);
    uint4 v0v = rna4(*(const uint4*)&Vb[vr * ND + vc]);
    uint4 v1v = rna4(*(const uint4*)&Vb[vr * ND + vc + 4]);
    uint4 v2v = rna4(*(const uint4*)&Vb[vr * ND + vc + 8]);
    uint4 v3v = rna4(*(const uint4*)&Vb[vr * ND + vc + 12]);

    {
        float* Ad = At;  float* Bd = Bs;
        Ad[abase]     = __uint_as_float(a0v.x);
        Ad[abase + 2] = __uint_as_float(a0v.y);
        Ad[abase + 4] = __uint_as_float(a0v.z);
        Ad[abase + 6] = __uint_as_float(a0v.w);
        *(float2*)&Bd[bbase]      = make_float2(__uint_as_float(v0v.x), __uint_as_float(v2v.x));
        *(float2*)&Bd[bbase + 4]  = make_float2(__uint_as_float(v0v.y), __uint_as_float(v2v.y));
        *(float2*)&Bd[bbase + 8]  = make_float2(__uint_as_float(v0v.z), __uint_as_float(v2v.z));
        *(float2*)&Bd[bbase + 12] = make_float2(__uint_as_float(v0v.w), __uint_as_float(v2v.w));
        *(float2*)&Bd[bbase + 16] = make_float2(__uint_as_float(v1v.x), __uint_as_float(v3v.x));
        *(float2*)&Bd[bbase + 20] = make_float2(__uint_as_float(v1v.y), __uint_as_float(v3v.y));
        *(float2*)&Bd[bbase + 24] = make_float2(__uint_as_float(v1v.z), __uint_as_float(v3v.z));
        *(float2*)&Bd[bbase + 28] = make_float2(__uint_as_float(v1v.w), __uint_as_float(v3v.w));
    }
    __syncthreads();

    float acc[4][4] = {};

    for (int tt = 0; tt < NSK / 32; tt++) {
        int cur = tt & 1;
        if (tt + 1 < NSK / 32) {
            int k0 = (tt + 1) * 32;
            a0v = rna4(*(const uint4*)&Ab[ar * NSK + k0 + akc]);
            v0v = rna4(*(const uint4*)&Vb[(k0 + vr) * ND + vc]);
            v1v = rna4(*(const uint4*)&Vb[(k0 + vr) * ND + vc + 4]);
            v2v = rna4(*(const uint4*)&Vb[(k0 + vr) * ND + vc + 8]);
            v3v = rna4(*(const uint4*)&Vb[(k0 + vr) * ND + vc + 12]);
        }
        const float* Ac = At + cur * AT_BUF;
        const float* Bc = Bs + cur * BS_BUF;

#pragma unroll
        for (int k8 = 0; k8 < 4; k8++) {
            int kb = k8 * 8;
            // A fragments: 2 x LDS.64 (fa0,fa2) and (fa1,fa3)
            uint2 fal = *(const uint2*)&Ac[(qs + g) * AT_PAD + kb + 2 * t];
            uint2 fah = *(const uint2*)&Ac[(qs + g + 8) * AT_PAD + kb + 2 * t];
            // B fragments: 2 x LDS.128 (n=0..3 for rows kb+t, kb+t+4)
            uint4 fbl = *(const uint4*)&Bc[(kb + t) * BS_PAD + ds + 4 * g];
            uint4 fbh = *(const uint4*)&Bc[(kb + t + 4) * BS_PAD + ds + 4 * g];
            asm volatile(
                "mma.sync.aligned.m16n8k8.row.col.f32.tf32.tf32.f32 "
                "{%0,%1,%2,%3}, {%4,%5,%6,%7}, {%8,%9}, {%0,%1,%2,%3};"
                : "+f"(acc[0][0]), "+f"(acc[0][1]), "+f"(acc[0][2]), "+f"(acc[0][3])
                : "r"(fal.x), "r"(fah.x), "r"(fal.y), "r"(fah.y), "r"(fbl.x), "r"(fbh.x));
            asm volatile(
                "mma.sync.aligned.m16n8k8.row.col.f32.tf32.tf32.f32 "
                "{%0,%1,%2,%3}, {%4,%5,%6,%7}, {%8,%9}, {%0,%1,%2,%3};"
                : "+f"(acc[1][0]), "+f"(acc[1][1]), "+f"(acc[1][2]), "+f"(acc[1][3])
                : "r"(fal.x), "r"(fah.x), "r"(fal.y), "r"(fah.y), "r"(fbl.y), "r"(fbh.y));
            asm volatile(
                "mma.sync.aligned.m16n8k8.row.col.f32.tf32.tf32.f32 "
                "{%0,%1,%2,%3}, {%4,%5,%6,%7}, {%8,%9}, {%0,%1,%2,%3};"
                : "+f"(acc[2][0]), "+f"(acc[2][1]), "+f"(acc[2][2]), "+f"(acc[2][3])
                : "r"(fal.x), "r"(fah.x), "r"(fal.y), "r"(fah.y), "r"(fbl.z), "r"(fbh.z));
            asm volatile(
                "mma.sync.aligned.m16n8k8.row.col.f32.tf32.tf32.f32 "
                "{%0,%1,%2,%3}, {%4,%5,%6,%7}, {%8,%9}, {%0,%1,%2,%3};"
                : "+f"(acc[3][0]), "+f"(acc[3][1]), "+f"(acc[3][2]), "+f"(acc[3][3])
                : "r"(fal.x), "r"(fah.x), "r"(fal.y), "r"(fah.y), "r"(fbl.w), "r"(fbh.w));
        }

        if (tt + 1 < NSK / 32) {
            int nxt = cur ^ 1;
            float* Ad = At + nxt * AT_BUF;
            float* Bd = Bs + nxt * BS_BUF;
            Ad[abase]     = __uint_as_float(a0v.x);
            Ad[abase + 2] = __uint_as_float(a0v.y);
            Ad[abase + 4] = __uint_as_float(a0v.z);
            Ad[abase + 6] = __uint_as_float(a0v.w);
            *(float2*)&Bd[bbase]      = make_float2(__uint_as_float(v0v.x), __uint_as_float(v2v.x));
            *(float2*)&Bd[bbase + 4]  = make_float2(__uint_as_float(v0v.y), __uint_as_float(v2v.y));
            *(float2*)&Bd[bbase + 8]  = make_float2(__uint_as_float(v0v.z), __uint_as_float(v2v.z));
            *(float2*)&Bd[bbase + 12] = make_float2(__uint_as_float(v0v.w), __uint_as_float(v2v.w));
            *(float2*)&Bd[bbase + 16] = make_float2(__uint_as_float(v1v.x), __uint_as_float(v3v.x));
            *(float2*)&Bd[bbase + 20] = make_float2(__uint_as_float(v1v.y), __uint_as_float(v3v.y));
            *(float2*)&Bd[bbase + 24] = make_float2(__uint_as_float(v1v.z), __uint_as_float(v3v.z));
            *(float2*)&Bd[bbase + 28] = make_float2(__uint_as_float(v1v.w), __uint_as_float(v3v.w));
        }
        __syncthreads();
    }

    // epilogue: c0:(g, 2t) c1:(g, 2t+1) c2:(g+8, 2t) c3:(g+8, 2t+1)
    float* Ob = out + (b * NSQ + q0) * ND + d0;
#pragma unroll
    for (int n = 0; n < 4; n++) {
        int dcol = ds + n * 8 + 2 * t;
        float2 lo = make_float2(acc[n][0], acc[n][1]);
        float2 hi = make_float2(acc[n][2], acc[n][3]);
        *(float2*)&Ob[(qs + g) * ND + dcol]     = lo;
        *(float2*)&Ob[(qs + g + 8) * ND + dcol] = hi;
    }
}

// ---------------------------------------------------------------------------
#define SMEM_SC ((TQ * NS + NS + NSK + 16 + KT * KMP + TQ * SCP) * 4)

extern "C" void kernel_launch(void* const* d_in, const int* in_sizes, int n_in,
                              void* d_out, int out_size) {
    const float* query = (const float*)d_in[0];
    const float* key   = (const float*)d_in[1];
    const float* value = (const float*)d_in[2];
    const int*   mask  = (const int*)d_in[3];
    const float* Wq = (const float*)d_in[4];
    const float* bq = (const float*)d_in[5];
    const float* Wk = (const float*)d_in[6];
    const float* bk = (const float*)d_in[7];
    const float* W1 = (const float*)d_in[8];
    const float* b1 = (const float*)d_in[9];
    const float* W2 = (const float*)d_in[10];
    const float* b2 = (const float*)d_in[11];

    float* out  = (float*)d_out;
    float* attn = out + NB * NSQ * ND;

    cudaFuncSetAttribute(score_kernel,
                         cudaFuncAttributeMaxDynamicSharedMemorySize, SMEM_SC);
    cudaFuncSetAttribute(av_kernel,
                         cudaFuncAttributeMaxDynamicSharedMemorySize, SMEM_AV);

    fold_kernel<<<dim3(65, 2), 128>>>(Wq, Wk, W1, bq, bk, b1, W2);
    proj_kernel<<<dim3(64, 2), 256>>>(query, key, W2);
    score_kernel<<<NB * NSQ / TQ, 128, SMEM_SC>>>(mask, b2, attn);
    av_kernel<<<dim3(4, 16, 4), 256, SMEM_AV>>>(attn, value, out);
}

// round 16
// speedup vs baseline: 1.1885x; 1.1885x over previous
#include <cuda_runtime.h>

#define NB  4
#define NSQ 512
#define NSK 512
#define ND  512
#define NS  128

typedef unsigned long long ull;

// ---- packed f32x2 helpers ----
__device__ __forceinline__ void fma2(ull& d, ull a, ull b) {
    asm("fma.rn.f32x2 %0, %1, %2, %0;" : "+l"(d) : "l"(a), "l"(b));
}
__device__ __forceinline__ ull add2(ull a, ull b) {
    ull r; asm("add.rn.f32x2 %0, %1, %2;" : "=l"(r) : "l"(a), "l"(b)); return r;
}
__device__ __forceinline__ ull pack2(float x, float y) {
    ull r; asm("mov.b64 %0, {%1, %2};" : "=l"(r) : "f"(x), "f"(y)); return r;
}
__device__ __forceinline__ float2 unpack2(ull v) {
    float2 r; asm("mov.b64 {%0, %1}, %2;" : "=f"(r.x), "=f"(r.y) : "l"(v)); return r;
}

#define SMASK 0x7fffffff7fffffffULL

// ---- cp.async helpers ----
__device__ __forceinline__ unsigned smem_u32(const void* p) {
    unsigned a;
    asm("{ .reg .u64 t; cvta.to.shared.u64 t, %1; cvt.u32.u64 %0, t; }"
        : "=r"(a) : "l"(p));
    return a;
}
#define CP_ASYNC16(dst_u32, src_ptr) \
    asm volatile("cp.async.ca.shared.global [%0], [%1], 16;" \
                 :: "r"(dst_u32), "l"(src_ptr))
#define CP_COMMIT()  asm volatile("cp.async.commit_group;" ::: "memory")
#define CP_WAIT1()   asm volatile("cp.async.wait_group 1;" ::: "memory")

// ---- scratch (allocation-free) ----
__device__ __align__(16) float g_Wqh[ND * NS];
__device__ __align__(16) float g_Wkh[ND * NS];
__device__ __align__(16) float g_cA[NS];
__device__ __align__(16) float g_cK[NS];
__device__ __align__(16) float g_sg[NS];            // +-0.5 by sign of w2
__device__ __align__(16) float g_A2[NB * NSQ * NS]; // (q@Wqh + cA) * w2
__device__ __align__(16) float g_K2[NB * NSK * NS]; // (k@Wkh + cK) * w2
__device__ __align__(16) float g_CA[NB * NSQ];      // 0.5 * rowsum(A2)
__device__ __align__(16) float g_CK[NB * NSK];      // 0.5 * rowsum(K2)

// ---------------------------------------------------------------------------
// fold: Wqh = Wq @ W1[:S], Wkh = Wk @ W1[S:]  (+ bias/sg in block x==64)
// ---------------------------------------------------------------------------
__global__ void fold_kernel(const float* __restrict__ Wq,
                            const float* __restrict__ Wk,
                            const float* __restrict__ W1,
                            const float* __restrict__ bq,
                            const float* __restrict__ bk,
                            const float* __restrict__ b1,
                            const float* __restrict__ W2) {
    int v = blockIdx.y, s = threadIdx.x;
    if (blockIdx.x == 64) {
        if (v == 0) {
            float a = b1[s];
#pragma unroll 8
            for (int t = 0; t < NS; t++) a = fmaf(bq[t], W1[t * NS + s], a);
            g_cA[s] = a;
            g_sg[s] = (W2[s] >= 0.f) ? 0.5f : -0.5f;
        } else {
            float c = 0.f;
#pragma unroll 8
            for (int t = 0; t < NS; t++) c = fmaf(bk[t], W1[(NS + t) * NS + s], c);
            g_cK[s] = c;
        }
        return;
    }
    int d0 = blockIdx.x * 8;
    __shared__ float wr[8][NS];
    const float* Wsrc = v ? Wk : Wq;
#pragma unroll
    for (int j = 0; j < 8; j++) wr[j][s] = Wsrc[(d0 + j) * NS + s];
    __syncthreads();
    const float* W1p = W1 + (v ? NS * NS : 0);
    float acc[8] = {};
#pragma unroll 8
    for (int t = 0; t < NS; t++) {
        float w = W1p[t * NS + s];
#pragma unroll
        for (int j = 0; j < 8; j++) acc[j] = fmaf(wr[j][t], w, acc[j]);
    }
    float* O = v ? g_Wkh : g_Wqh;
#pragma unroll
    for (int j = 0; j < 8; j++) O[(d0 + j) * NS + s] = acc[j];
}

// ---------------------------------------------------------------------------
// proj: A2 = (X @ Wfold + cb) * w2, plus CA = 0.5*rowsum(A2)  (unchanged)
// ---------------------------------------------------------------------------
#define ASP 36
#define BSP 132

__global__ __launch_bounds__(256) void proj_kernel(const float* __restrict__ Xq,
                                                   const float* __restrict__ Xk,
                                                   const float* __restrict__ W2) {
    int v = blockIdx.y;
    const float* X    = v ? Xk : Xq;
    const float* Wf   = v ? g_Wkh : g_Wqh;
    const float* bias = v ? g_cK : g_cA;
    float* O          = v ? g_K2 : g_A2;
    float* CS         = v ? g_CK : g_CA;

    int m0  = blockIdx.x * 32;
    int tid = threadIdx.x;
    int w   = tid >> 5, lane = tid & 31;
    int qc  = lane >> 2, dc = lane & 3;

    __shared__ float As[16][ASP];
    __shared__ float Bs[16][BSP];
    __shared__ float red[8][32];

    int r  = tid >> 3, c2 = (tid & 7) * 2;
    int rb = tid >> 4, cw = (tid & 15) * 8;

    float2 xv = *(const float2*)&X[(m0 + r) * ND + c2];
    float4 w0 = *(const float4*)&Wf[rb * NS + cw];
    float4 w1 = *(const float4*)&Wf[rb * NS + cw + 4];

    ull acc[4][2] = {};
    int db = w * 16 + dc * 4;

    for (int t = 0; t < ND / 16; t++) {
        As[c2][r] = xv.x; As[c2 + 1][r] = xv.y;
        *(float4*)&Bs[rb][cw]     = w0;
        *(float4*)&Bs[rb][cw + 4] = w1;
        __syncthreads();
        if (t + 1 < ND / 16) {
            int k0 = (t + 1) * 16;
            xv = *(const float2*)&X[(m0 + r) * ND + k0 + c2];
            w0 = *(const float4*)&Wf[(k0 + rb) * NS + cw];
            w1 = *(const float4*)&Wf[(k0 + rb) * NS + cw + 4];
        }
#pragma unroll
        for (int kk = 0; kk < 16; kk++) {
            float4 a = *(float4*)&As[kk][qc * 4];
            ulonglong2 bv = *(ulonglong2*)&Bs[kk][db];
            ull p0 = pack2(a.x, a.x), p1 = pack2(a.y, a.y);
            ull p2 = pack2(a.z, a.z), p3 = pack2(a.w, a.w);
            fma2(acc[0][0], p0, bv.x); fma2(acc[0][1], p0, bv.y);
            fma2(acc[1][0], p1, bv.x); fma2(acc[1][1], p1, bv.y);
            fma2(acc[2][0], p2, bv.x); fma2(acc[2][1], p2, bv.y);
            fma2(acc[3][0], p3, bv.x); fma2(acc[3][1], p3, bv.y);
        }
        __syncthreads();
    }

    float4 cbv = *(const float4*)&bias[db];
    float4 w2v = *(const float4*)&W2[db];
    float rsum[4];
#pragma unroll
    for (int j = 0; j < 4; j++) {
        int row = m0 + qc * 4 + j;
        float2 p0 = unpack2(acc[j][0]), p1 = unpack2(acc[j][1]);
        float4 o;
        o.x = (p0.x + cbv.x) * w2v.x; o.y = (p0.y + cbv.y) * w2v.y;
        o.z = (p1.x + cbv.z) * w2v.z; o.w = (p1.y + cbv.w) * w2v.w;
        *(float4*)&O[row * NS + db] = o;
        rsum[j] = o.x + o.y + o.z + o.w;
    }
#pragma unroll
    for (int j = 0; j < 4; j++) {
        rsum[j] += __shfl_xor_sync(0xffffffffu, rsum[j], 1);
        rsum[j] += __shfl_xor_sync(0xffffffffu, rsum[j], 2);
    }
    if (dc == 0) {
#pragma unroll
        for (int j = 0; j < 4; j++) red[w][qc * 4 + j] = rsum[j];
    }
    __syncthreads();
    if (tid < 32) {
        float s = 0.f;
#pragma unroll
        for (int ww = 0; ww < 8; ww++) s += red[ww][tid];
        CS[m0 + tid] = 0.5f * s;
    }
}

// ---------------------------------------------------------------------------
// scores + softmax + attn write (R9 version) — unchanged
// ---------------------------------------------------------------------------
#define TQ  8
#define KT  64
#define KMP 132
#define SCP 516

__global__ __launch_bounds__(128) void score_kernel(const int* __restrict__ mask,
                                                    const float* __restrict__ b2,
                                                    float* __restrict__ attn_out) {
    extern __shared__ float sm[];
    float* qcs = sm;                    // TQ*NS  = 1024 f
    float* sgs = qcs + TQ * NS;         // 128 f
    float* cks = sgs + NS;              // 512 f
    float* cas = cks + NSK;             // 16 f
    float* kms = cas + 16;              // KT*KMP = 8448 f
    float* scT = kms + KT * KMP;        // TQ*516 = 4128 f

    int bx = blockIdx.x;
    int b  = bx >> 6;
    int q0 = (bx & 63) * TQ;
    int tid = threadIdx.x;
    int kk = tid & 63;
    int qh = (tid >> 6) * 4;            // 0 or 4

    {
        const float4* A4 = (const float4*)&g_A2[(b * NSQ + q0) * NS];
        ((float4*)qcs)[tid]       = A4[tid];
        ((float4*)qcs)[tid + 128] = A4[tid + 128];
        if (tid < 32) ((float4*)sgs)[tid] = ((const float4*)g_sg)[tid];
        ((float4*)cks)[tid] = ((const float4*)(g_CK + b * NSK))[tid];
        if (tid < TQ) cas[tid] = g_CA[b * NSQ + q0 + tid] + b2[0];
    }

    const float* qp = qcs + qh * NS;

    for (int k0 = 0; k0 < NSK; k0 += KT) {
        __syncthreads();
        const float4* K4 = (const float4*)&g_K2[(b * NSK + k0) * NS];
#pragma unroll
        for (int i = 0; i < 16; i++) {
            int idx = i * 128 + tid;
            int kr = idx >> 5, s4 = idx & 31;
            *(float4*)&kms[kr * KMP + s4 * 4] = K4[idx];
        }
        __syncthreads();

        ull acc[4] = {};
#pragma unroll 8
        for (int s = 0; s < NS; s += 4) {
            ulonglong2 kv = *(ulonglong2*)&kms[kk * KMP + s];
            ulonglong2 sg = *(ulonglong2*)&sgs[s];
#pragma unroll
            for (int q = 0; q < 4; q++) {
                ulonglong2 qv = *(ulonglong2*)&qp[q * NS + s];
                ull x0 = add2(qv.x, kv.x) & SMASK;
                ull x1 = add2(qv.y, kv.y) & SMASK;
                fma2(acc[q], sg.x, x0);
                fma2(acc[q], sg.y, x1);
            }
        }

        int kg = k0 + kk;
        float ckv = cks[kg];
        const int* mrow = mask + (b * NSQ + q0 + qh) * NSK + kg;
#pragma unroll
        for (int q = 0; q < 4; q++) {
            float2 p = unpack2(acc[q]);
            float s = p.x + p.y + cas[qh + q] + ckv;
            if (mrow[q * NSK] == 0) s = -1e9f;
            scT[(qh + q) * SCP + kg] = s;
        }
    }
    __syncthreads();

    // softmax: warp w handles q = 2w, 2w+1; write normalized attn to gmem
    {
        int w = tid >> 5, lane = tid & 31;
#pragma unroll
        for (int qq = 0; qq < 2; qq++) {
            int q = w * 2 + qq;
            float4 v[4];
            float mx = -3.0e38f;
#pragma unroll
            for (int j = 0; j < 4; j++) {
                v[j] = *(float4*)&scT[q * SCP + j * 128 + lane * 4];
                mx = fmaxf(mx, fmaxf(fmaxf(v[j].x, v[j].y), fmaxf(v[j].z, v[j].w)));
            }
#pragma unroll
            for (int o = 16; o; o >>= 1) mx = fmaxf(mx, __shfl_xor_sync(0xffffffffu, mx, o));
            float sum = 0.f;
#pragma unroll
            for (int j = 0; j < 4; j++) {
                v[j].x = __expf(v[j].x - mx); v[j].y = __expf(v[j].y - mx);
                v[j].z = __expf(v[j].z - mx); v[j].w = __expf(v[j].w - mx);
                sum += v[j].x + v[j].y + v[j].z + v[j].w;
            }
#pragma unroll
            for (int o = 16; o; o >>= 1) sum += __shfl_xor_sync(0xffffffffu, sum, o);
            float inv = 1.0f / sum;
            float* arow = attn_out + (b * NSQ + q0 + q) * NSK;
#pragma unroll
            for (int j = 0; j < 4; j++) {
                float4 wv;
                wv.x = v[j].x * inv; wv.y = v[j].y * inv;
                wv.z = v[j].z * inv; wv.w = v[j].w * inv;
                *(float4*)&arow[j * 128 + lane * 4] = wv;
            }
        }
    }
}

// ---------------------------------------------------------------------------
// AV GEMM on tensor cores with 3-stage cp.async pipeline (MLP fix).
// BM=32 q x BN=128 d x BK=32, 256 thr, grid (4,16,4)=256 -> 2 CTA/SM.
// cp.async 16B copies (no register staging, deep in-flight), commit/wait per
// tile. tf32 truncation bias corrected at epilogue: acc *= 1/(1-2^-12)^2.
// Fragment gather = R12 verified conflict-free scalar pattern (pads 36/136).
// ---------------------------------------------------------------------------
#define AT_PAD 36
#define BS_PAD 136
#define STAGE_F (32 * AT_PAD + 32 * BS_PAD)       // 5504 floats per stage
#define NSTAGE 3
#define SMEM_AV (NSTAGE * STAGE_F * 4)            // 66048 B
#define TF32_BIAS 1.00048840f                     // 1/(1-2^-12)^2

__global__ __launch_bounds__(256) void av_kernel(const float* __restrict__ attn,
                                                 const float* __restrict__ Vv,
                                                 float* __restrict__ out) {
    extern __shared__ float avsm[];
    // stage s: At at avsm + s*STAGE_F, Bs at avsm + s*STAGE_F + 32*AT_PAD

    int b  = blockIdx.z;
    int q0 = blockIdx.y * 32;
    int d0 = blockIdx.x * 128;
    int tid = threadIdx.x;
    int w = tid >> 5, lane = tid & 31;
    int g = lane >> 2, t = lane & 3;
    int qs = (w >> 2) * 16;            // warp q-strip (0, 16)
    int ds = (w & 3) * 32;             // warp d-strip (0, 32, 64, 96)

    const float* Ab = attn + (b * NSQ + q0) * NSK;
    const float* Vb = Vv + b * NSK * ND + d0;

    unsigned smbase = smem_u32(avsm);

    // cp.async loader coords:
    // A: 256 chunks of 16B (32 rows x 8). thread -> chunk tid.
    int a_r = tid >> 3, a_c = (tid & 7) * 4;
    // B: 1024 chunks (32 rows x 32). thread -> chunks tid + j*256.
    // Issue one tile's cp.asyncs into stage slot.
    auto issue_tile = [&](int tile, int slot) {
        unsigned at_u = smbase + (unsigned)(slot * STAGE_F) * 4u;
        unsigned bs_u = at_u + 32u * AT_PAD * 4u;
        int k0 = tile * 32;
        CP_ASYNC16(at_u + (a_r * AT_PAD + a_c) * 4u, &Ab[a_r * NSK + k0 + a_c]);
#pragma unroll
        for (int j = 0; j < 4; j++) {
            int c = tid + j * 256;
            int br = c >> 5, bo = (c & 31) * 4;
            CP_ASYNC16(bs_u + (br * BS_PAD + bo) * 4u, &Vb[(k0 + br) * ND + bo]);
        }
    };

    // prologue: stages for tiles 0, 1
    issue_tile(0, 0); CP_COMMIT();
    issue_tile(1, 1); CP_COMMIT();

    float acc[4][4] = {};

    for (int tt = 0; tt < NSK / 32; tt++) {
        CP_WAIT1();                    // tile tt's group complete
        __syncthreads();               // make all threads' copies visible

        int slot = tt % NSTAGE;
        const float* Ac = avsm + slot * STAGE_F;
        const float* Bc = Ac + 32 * AT_PAD;

#pragma unroll
        for (int k8 = 0; k8 < 4; k8++) {
            int kb = k8 * 8;
            unsigned fa0 = __float_as_uint(Ac[(qs + g) * AT_PAD + kb + t]);
            unsigned fa1 = __float_as_uint(Ac[(qs + g + 8) * AT_PAD + kb + t]);
            unsigned fa2 = __float_as_uint(Ac[(qs + g) * AT_PAD + kb + t + 4]);
            unsigned fa3 = __float_as_uint(Ac[(qs + g + 8) * AT_PAD + kb + t + 4]);
#pragma unroll
            for (int n = 0; n < 4; n++) {
                unsigned fb0 = __float_as_uint(Bc[(kb + t) * BS_PAD + ds + n * 8 + g]);
                unsigned fb1 = __float_as_uint(Bc[(kb + t + 4) * BS_PAD + ds + n * 8 + g]);
                asm volatile(
                    "mma.sync.aligned.m16n8k8.row.col.f32.tf32.tf32.f32 "
                    "{%0,%1,%2,%3}, {%4,%5,%6,%7}, {%8,%9}, {%0,%1,%2,%3};"
                    : "+f"(acc[n][0]), "+f"(acc[n][1]), "+f"(acc[n][2]), "+f"(acc[n][3])
                    : "r"(fa0), "r"(fa1), "r"(fa2), "r"(fa3), "r"(fb0), "r"(fb1));
            }
        }

        __syncthreads();               // tile tt readers done before slot reuse
        if (tt + 2 < NSK / 32)
            issue_tile(tt + 2, (tt + 2) % NSTAGE);
        CP_COMMIT();                   // commit every iteration (group bookkeeping)
    }

    // epilogue with tf32 truncation bias correction
    float* Ob = out + (b * NSQ + q0) * ND + d0;
#pragma unroll
    for (int n = 0; n < 4; n++) {
        int dcol = ds + n * 8 + 2 * t;
        float2 lo = make_float2(acc[n][0] * TF32_BIAS, acc[n][1] * TF32_BIAS);
        float2 hi = make_float2(acc[n][2] * TF32_BIAS, acc[n][3] * TF32_BIAS);
        *(float2*)&Ob[(qs + g) * ND + dcol]     = lo;
        *(float2*)&Ob[(qs + g + 8) * ND + dcol] = hi;
    }
}

// ---------------------------------------------------------------------------
#define SMEM_SC ((TQ * NS + NS + NSK + 16 + KT * KMP + TQ * SCP) * 4)

extern "C" void kernel_launch(void* const* d_in, const int* in_sizes, int n_in,
                              void* d_out, int out_size) {
    const float* query = (const float*)d_in[0];
    const float* key   = (const float*)d_in[1];
    const float* value = (const float*)d_in[2];
    const int*   mask  = (const int*)d_in[3];
    const float* Wq = (const float*)d_in[4];
    const float* bq = (const float*)d_in[5];
    const float* Wk = (const float*)d_in[6];
    const float* bk = (const float*)d_in[7];
    const float* W1 = (const float*)d_in[8];
    const float* b1 = (const float*)d_in[9];
    const float* W2 = (const float*)d_in[10];
    const float* b2 = (const float*)d_in[11];

    float* out  = (float*)d_out;
    float* attn = out + NB * NSQ * ND;

    cudaFuncSetAttribute(score_kernel,
                         cudaFuncAttributeMaxDynamicSharedMemorySize, SMEM_SC);
    cudaFuncSetAttribute(av_kernel,
                         cudaFuncAttributeMaxDynamicSharedMemorySize, SMEM_AV);

    fold_kernel<<<dim3(65, 2), 128>>>(Wq, Wk, W1, bq, bk, b1, W2);
    proj_kernel<<<dim3(64, 2), 256>>>(query, key, W2);
    score_kernel<<<NB * NSQ / TQ, 128, SMEM_SC>>>(mask, b2, attn);
    av_kernel<<<dim3(4, 16, 4), 256, SMEM_AV>>>(attn, value, out);
}